// round 11
// baseline (speedup 1.0000x reference)
#include <cuda_runtime.h>
#include <math.h>

#define N_    2
#define L_    512
#define H_    24
#define QK_   16
#define V_    16
#define HID_  128
#define CH_   504
#define EPS_  1e-6f
#define KPAD  20

// ---------------- scratch ----------------
__device__ float  g_q [N_*L_*H_*QK_];
__device__ float  g_kT[N_*H_*QK_*L_];
__device__ float  g_vT[N_*H_*V_ *L_];
__device__ float  g_a [N_*H_*L_*3];
__device__ float  g_b [N_*H_*L_*3];
__device__ float  g_cc[N_*L_*CH_];
__device__ float  g_uw[(size_t)N_*L_*L_];      // |R_i^T t_j|^2   2MB
__device__ float  g_st[(size_t)N_*H_*L_*L_];   // st, then overwritten with p
__device__ float  g_is[N_*H_*L_];              // 1/s per (n,h,i)

__device__ __forceinline__ float rsqrt_fast(float x) {
    float r; asm("rsqrt.approx.f32 %0,%1;" : "=f"(r) : "f"(x)); return r;
}
__device__ __forceinline__ float ex2_fast(float x) {
    float r; asm("ex2.approx.f32 %0,%1;" : "=f"(r) : "f"(x)); return r;
}
__device__ __forceinline__ float acos_fast(float x) {
    float ax = fminf(fabsf(x), 1.0f);
    float s; asm("sqrt.approx.f32 %0,%1;" : "=f"(s) : "f"(1.0f - ax));
    float p = fmaf(ax, -0.0187293f, 0.0742610f);
    p = fmaf(ax, p, -0.2121144f);
    p = fmaf(ax, p, 1.5707288f);
    float r = s * p;
    return x < 0.f ? 3.14159265359f - r : r;
}

// ================= kernel A: fused projections (proven ~22us) =================
#define PJS 68

__global__ void __launch_bounds__(256) proj_kernel(
    const float* __restrict__ x,
    const float* __restrict__ Wq, const float* __restrict__ Wk,
    const float* __restrict__ Wv, const float* __restrict__ bv,
    const float* __restrict__ Wa, const float* __restrict__ ba,
    const float* __restrict__ Wb, const float* __restrict__ bb)
{
    __shared__ float xs[32*PJS];
    __shared__ float ws[32*PJS];

    const int tid = threadIdx.x;
    const int rt  = blockIdx.x;
    const int ct  = blockIdx.y;
    const int tx = tid & 15;
    const int ty = tid >> 4;

    float acc[4][4];
    #pragma unroll
    for (int r = 0; r < 4; r++)
        #pragma unroll
        for (int c = 0; c < 4; c++) acc[r][c] = 0.f;

    #pragma unroll 1
    for (int chunk = 0; chunk < 4; chunk++) {
        __syncthreads();
        #pragma unroll
        for (int it = 0; it < 2; it++) {
            const int idx = it*256 + tid;
            const int kq = idx & 7;
            const int m  = idx >> 3;
            const float4 v = *(const float4*)(x + (size_t)(rt*64 + m)*HID_ + chunk*32 + kq*4);
            xs[(kq*4+0)*PJS + m] = v.x;
            xs[(kq*4+1)*PJS + m] = v.y;
            xs[(kq*4+2)*PJS + m] = v.z;
            xs[(kq*4+3)*PJS + m] = v.w;
        }
        #pragma unroll
        for (int it = 0; it < 2; it++) {
            const int idx = it*256 + tid;
            const int kq = idx & 7;
            const int cl = idx >> 3;
            const int c  = min(ct*64 + cl, 1295);
            const float* wrow;
            if      (c <  384) wrow = Wq + (size_t)c*HID_;
            else if (c <  768) wrow = Wk + (size_t)(c- 384)*HID_;
            else if (c < 1152) wrow = Wv + (size_t)(c- 768)*HID_;
            else if (c < 1224) wrow = Wa + (size_t)(c-1152)*HID_;
            else               wrow = Wb + (size_t)(c-1224)*HID_;
            const float4 v = *(const float4*)(wrow + chunk*32 + kq*4);
            ws[(kq*4+0)*PJS + cl] = v.x;
            ws[(kq*4+1)*PJS + cl] = v.y;
            ws[(kq*4+2)*PJS + cl] = v.z;
            ws[(kq*4+3)*PJS + cl] = v.w;
        }
        __syncthreads();

        #pragma unroll
        for (int k = 0; k < 32; k++) {
            const float4 xv = *(const float4*)(xs + k*PJS + tx*4);
            const float4 wv = *(const float4*)(ws + k*PJS + ty*4);
            const float xa[4] = {xv.x, xv.y, xv.z, xv.w};
            const float wa[4] = {wv.x, wv.y, wv.z, wv.w};
            #pragma unroll
            for (int r = 0; r < 4; r++)
                #pragma unroll
                for (int c = 0; c < 4; c++)
                    acc[r][c] = fmaf(xa[r], wa[c], acc[r][c]);
        }
    }

    #pragma unroll
    for (int r = 0; r < 4; r++) {
        const int gi = rt*64 + tx*4 + r;
        const int n = gi >> 9, i = gi & 511;
        #pragma unroll
        for (int cv = 0; cv < 4; cv++) {
            const int c = ct*64 + ty*4 + cv;
            if (c >= 1296) continue;
            float val = acc[r][cv];
            if (c < 384) {
                g_q[(size_t)gi*384 + c] = val;
            } else if (c < 768) {
                int cc = c - 384; int h = cc >> 4, d = cc & 15;
                g_kT[((size_t)(n*H_ + h)*QK_ + d)*L_ + i] = val;
            } else if (c < 1152) {
                int cc = c - 768; int h = cc >> 4, d = cc & 15;
                g_vT[((size_t)(n*H_ + h)*V_ + d)*L_ + i] = val + bv[cc];
            } else if (c < 1224) {
                int cc = c - 1152; int h = cc/3, xx = cc - h*3;
                g_a[((size_t)(n*H_ + h)*L_ + i)*3 + xx] = val + ba[cc];
            } else {
                int cc = c - 1224; int h = cc/3, xx = cc - h*3;
                g_b[((size_t)(n*H_ + h)*L_ + i)*3 + xx] = val + bb[cc];
            }
        }
    }
}

// ================= kernel U: uw = |R_i^T t_j|^2 =================
__global__ void __launch_bounds__(256) u_kernel(
    const float* __restrict__ Rm, const float* __restrict__ t)
{
    __shared__ float4 ts4[L_];
    const int tid = threadIdx.x;
    const int n = blockIdx.y;
    const int i = blockIdx.x*8 + (tid >> 5);
    const int lane = tid & 31;

    for (int j = tid; j < L_; j += 256) {
        const float* tp = t + (size_t)(n*L_ + j)*3;
        ts4[j] = make_float4(tp[0], tp[1], tp[2], 0.f);
    }
    __syncthreads();

    const float* Rp = Rm + (size_t)(n*L_ + i)*9;
    const float R00=Rp[0],R01=Rp[1],R02=Rp[2],
                R10=Rp[3],R11=Rp[4],R12=Rp[5],
                R20=Rp[6],R21=Rp[7],R22=Rp[8];

    float* up = g_uw + (size_t)(n*L_ + i)*L_;
    #pragma unroll 2
    for (int it = 0; it < 16; it++) {
        const int j = it*32 + lane;
        const float4 tj = ts4[j];
        const float ux = R00*tj.x + R10*tj.y + R20*tj.z;
        const float uy = R01*tj.x + R11*tj.y + R21*tj.z;
        const float uz = R02*tj.x + R12*tj.y + R22*tj.z;
        up[j] = fmaf(ux,ux, fmaf(uy,uy, uz*uz));
    }
}

// ================= kernel S: st = c1*(q.k) + bias =================
__global__ void __launch_bounds__(256) st_kernel()
{
    __shared__ float qs[16*68];
    __shared__ float ksm[16*64];

    const int tid = threadIdx.x;
    const int i0 = blockIdx.x * 64;
    const int j0 = blockIdx.y * 64;
    const int nh = blockIdx.z;
    const int n = nh / H_, h = nh - n*H_;

    {
        const int il = tid >> 2, dq = tid & 3;
        const float4 v = *(const float4*)(g_q + (size_t)(n*L_ + i0 + il)*384 + h*16 + dq*4);
        qs[(dq*4+0)*68 + il] = v.x;
        qs[(dq*4+1)*68 + il] = v.y;
        qs[(dq*4+2)*68 + il] = v.z;
        qs[(dq*4+3)*68 + il] = v.w;
    }
    {
        const int dk = tid >> 4, j4 = tid & 15;
        const float4 v = *(const float4*)(g_kT + ((size_t)nh*16 + dk)*L_ + j0 + j4*4);
        *(float4*)(ksm + dk*64 + j4*4) = v;
    }
    __syncthreads();

    const int tx = tid & 15;
    const int ty = tid >> 4;

    float acc[4][4];
    #pragma unroll
    for (int r = 0; r < 4; r++)
        #pragma unroll
        for (int c = 0; c < 4; c++) acc[r][c] = 0.f;

    #pragma unroll
    for (int d = 0; d < 16; d++) {
        const float4 qv = *(const float4*)(qs + d*68 + ty*4);
        const float4 kv = *(const float4*)(ksm + d*64 + tx*4);
        const float qa[4] = {qv.x, qv.y, qv.z, qv.w};
        const float ka[4] = {kv.x, kv.y, kv.z, kv.w};
        #pragma unroll
        for (int r = 0; r < 4; r++)
            #pragma unroll
            for (int c = 0; c < 4; c++)
                acc[r][c] = fmaf(qa[r], ka[c], acc[r][c]);
    }

    const float C1 = 0.70710678118f * 0.25f * 1.44269504089f;
    const float BIAS = -4.0f * 1.44269504089f;
    #pragma unroll
    for (int r = 0; r < 4; r++) {
        const int i = i0 + ty*4 + r;
        float4 o;
        o.x = fmaf(C1, acc[r][0], BIAS);
        o.y = fmaf(C1, acc[r][1], BIAS);
        o.z = fmaf(C1, acc[r][2], BIAS);
        o.w = fmaf(C1, acc[r][3], BIAS);
        *(float4*)(g_st + ((size_t)nh*L_ + i)*L_ + j0 + tx*4) = o;
    }
}

// ================= kernel P: p generation + scalar sums =================
// Overwrites g_st with p; writes 1/s to g_is and the scalar concat outputs.
__global__ void __launch_bounds__(256) attn_p_kernel(
    const float* __restrict__ Rm, const float* __restrict__ t,
    const float* __restrict__ alpha, const float* __restrict__ beta)
{
    __shared__ float4 ts4[L_];

    const int tid = threadIdx.x;
    const int n = blockIdx.z, h = blockIdx.y;
    const int i0 = blockIdx.x * 32;

    for (int j = tid; j < L_; j += 256) {
        const float* tp = t + (size_t)(n*L_ + j)*3;
        ts4[j] = make_float4(tp[0], tp[1], tp[2], 0.f);
    }
    __syncthreads();

    const float LOG2E = 1.44269504089f;
    const float al = log1pf(expf(alpha[h])) * 0.70710678118f * LOG2E;
    const float be = log1pf(expf(beta[h]))  * 0.70710678118f * LOG2E;
    const int warp = tid >> 5, lane = tid & 31;
    const int nh = n*H_ + h;

    #pragma unroll 1
    for (int pass = 0; pass < 4; pass++) {
        const int i = i0 + warp*4 + pass;

        float w1x, w1y, w1z, w2x, w2y, w2z, cw, ca, c0, c1, c2;
        {
            const float* Rp = Rm + (size_t)(n*L_ + i)*9;
            const float R00=Rp[0],R01=Rp[1],R02=Rp[2],
                        R10=Rp[3],R11=Rp[4],R12=Rp[5],
                        R20=Rp[6],R21=Rp[7],R22=Rp[8];
            const float4 ti = ts4[i];
            const float* bp_ = g_b + ((size_t)nh*L_ + i)*3;
            c0 = R00*ti.x + R10*ti.y + R20*ti.z + bp_[0];
            c1 = R01*ti.x + R11*ti.y + R21*ti.z + bp_[1];
            c2 = R02*ti.x + R12*ti.y + R22*ti.z + bp_[2];
            cw = fmaf(c0,c0, fmaf(c1,c1, c2*c2));
            const float* ap = g_a + ((size_t)nh*L_ + i)*3;
            float a0=ap[0], a1=ap[1], a2=ap[2];
            const float inv = 1.0f/(sqrtf(a0*a0+a1*a1+a2*a2) + EPS_);
            a0 *= inv; a1 *= inv; a2 *= inv;
            ca = fmaf(c0,a0, fmaf(c1,a1, c2*a2));
            w1x = -2.f*(R00*c0 + R01*c1 + R02*c2);
            w1y = -2.f*(R10*c0 + R11*c1 + R12*c2);
            w1z = -2.f*(R20*c0 + R21*c1 + R22*c2);
            w2x = R00*a0 + R01*a1 + R02*a2;
            w2y = R10*a0 + R11*a1 + R12*a2;
            w2z = R20*a0 + R21*a1 + R22*a2;
        }

        const float* uwp = g_uw + (size_t)(n*L_ + i)*L_;
        float* stp = g_st + ((size_t)nh*L_ + i)*L_;

        float s=0.f, pt0=0.f, pt1=0.f, pt2=0.f, pth=0.f;

        #pragma unroll 4
        for (int it = 0; it < 16; it++) {
            const int j = it*32 + lane;
            const float uw = __ldg(uwp + j);
            const float st = stp[j];
            const float4 tj = ts4[j];

            float rr = fmaf(w1x,tj.x, fmaf(w1y,tj.y, fmaf(w1z,tj.z, uw + cw)));
            rr = fmaxf(rr, 1e-24f);
            const float ir = rsqrt_fast(rr);
            const float rs = rr * ir;
            const float rda = fmaf(w2x,tj.x, fmaf(w2y,tj.y, fmaf(w2z,tj.z, -ca)));
            const float th = acos_fast(rda * ir);
            float arg = fmaf(-al, rs, fmaf(-be, th, st));
            if (j == i) arg = -150.f;
            const float p = ex2_fast(arg);

            stp[j] = p;             // overwrite st with p
            s += p;
            pt0 = fmaf(p, tj.x, pt0);
            pt1 = fmaf(p, tj.y, pt1);
            pt2 = fmaf(p, tj.z, pt2);
            pth = fmaf(p, th,  pth);
        }

        #pragma unroll
        for (int off = 16; off > 0; off >>= 1) {
            s   += __shfl_xor_sync(0xffffffffu, s,   off);
            pt0 += __shfl_xor_sync(0xffffffffu, pt0, off);
            pt1 += __shfl_xor_sync(0xffffffffu, pt1, off);
            pt2 += __shfl_xor_sync(0xffffffffu, pt2, off);
            pth += __shfl_xor_sync(0xffffffffu, pth, off);
        }
        if (lane == 0) {
            const float inv = 1.0f / s;
            g_is[(size_t)nh*L_ + i] = inv;
            float* cc = g_cc + (size_t)(n*L_ + i)*CH_;
            const float* Rp = Rm + (size_t)(n*L_ + i)*9;
            const float ra0 = (Rp[0]*pt0 + Rp[3]*pt1 + Rp[6]*pt2)*inv - c0;
            const float ra1 = (Rp[1]*pt0 + Rp[4]*pt1 + Rp[7]*pt2)*inv - c1;
            const float ra2 = (Rp[2]*pt0 + Rp[5]*pt1 + Rp[8]*pt2)*inv - c2;
            cc[384 + h*3 + 0] = ra0;
            cc[384 + h*3 + 1] = ra1;
            cc[384 + h*3 + 2] = ra2;
            cc[456 + h] = sqrtf(ra0*ra0 + ra1*ra1 + ra2*ra2);
            cc[480 + h] = pth*inv;
        }
    }
}

// ================= kernel PV: av = (P @ V^T) * inv_s =================
// 64 i-rows x 16 d per block; jtile = 128.
#define PVS 129
#define PV_SMEM ((L_*KPAD + 64*PVS)*4)   // 40960 + 33024 = 73984 B

__global__ void __launch_bounds__(256) pv_kernel()
{
    extern __shared__ float sm[];
    float* vs = sm;               // [512][20]
    float* ps = sm + L_*KPAD;     // [64][129]

    const int tid = threadIdx.x;
    const int n = blockIdx.z, h = blockIdx.y;
    const int i0 = blockIdx.x * 64;
    const int nh = n*H_ + h;

    const float* vb = g_vT + (size_t)nh*V_*L_;
    for (int idx = tid; idx < QK_*L_; idx += 256) {
        int d = idx >> 9, j = idx & 511;
        vs[j*KPAD + d] = vb[idx];
    }

    const int il = tid >> 2;     // 0..63
    const int d4 = tid & 3;      // 0..3
    float4 acc = make_float4(0.f, 0.f, 0.f, 0.f);

    #pragma unroll 1
    for (int jt = 0; jt < 4; jt++) {
        __syncthreads();
        // stage p tile: 64 rows x 128 j
        #pragma unroll
        for (int k = 0; k < 8; k++) {
            const int fidx = k*256 + tid;        // 0..2047 float4
            const int row = fidx >> 5;
            const int jj  = (fidx & 31) * 4;
            const float4 v = *(const float4*)(g_st + ((size_t)nh*L_ + i0 + row)*L_ + jt*128 + jj);
            float* pd = ps + row*PVS + jj;
            pd[0] = v.x; pd[1] = v.y; pd[2] = v.z; pd[3] = v.w;
        }
        __syncthreads();

        const float* pr = ps + il*PVS;
        const float* vr = vs + (jt*128)*KPAD + d4*4;
        #pragma unroll 4
        for (int j = 0; j < 128; j++) {
            const float p = pr[j];
            const float4 v4 = *(const float4*)(vr + j*KPAD);
            acc.x = fmaf(p, v4.x, acc.x);
            acc.y = fmaf(p, v4.y, acc.y);
            acc.z = fmaf(p, v4.z, acc.z);
            acc.w = fmaf(p, v4.w, acc.w);
        }
    }

    const float inv = g_is[(size_t)nh*L_ + i0 + il];
    float4 o;
    o.x = acc.x*inv; o.y = acc.y*inv; o.z = acc.z*inv; o.w = acc.w*inv;
    *(float4*)(g_cc + (size_t)(n*L_ + i0 + il)*CH_ + h*16 + d4*4) = o;
}

// ================= kernel C: output projection =================
__global__ void out_kernel(const float* __restrict__ Wp, const float* __restrict__ bp,
                           float* __restrict__ out)
{
    __shared__ __align__(16) float cs[8*CH_];
    const int tid = threadIdx.x;
    const int r0 = blockIdx.x * 8;

    for (int idx = tid; idx < 8*CH_; idx += 128)
        cs[idx] = g_cc[(size_t)r0*CH_ + idx];
    __syncthreads();

    float acc[8];
    #pragma unroll
    for (int r = 0; r < 8; r++) acc[r] = 0.f;

    const float4* w4 = (const float4*)(Wp + (size_t)tid*CH_);
    #pragma unroll 2
    for (int k4 = 0; k4 < CH_/4; k4++) {
        const float4 w = w4[k4];
        #pragma unroll
        for (int r = 0; r < 8; r++) {
            const float4 cv = ((const float4*)(cs + r*CH_))[k4];
            acc[r] += cv.x*w.x + cv.y*w.y + cv.z*w.z + cv.w*w.w;
        }
    }
    const float bbv = bp[tid];
    #pragma unroll
    for (int r = 0; r < 8; r++)
        out[(size_t)(r0 + r)*HID_ + tid] = acc[r] + bbv;
}

// ---------------- launch ----------------
extern "C" void kernel_launch(void* const* d_in, const int* in_sizes, int n_in,
                              void* d_out, int out_size)
{
    const float* x     = (const float*)d_in[0];
    const float* R     = (const float*)d_in[1];
    const float* t     = (const float*)d_in[2];
    const float* Wq    = (const float*)d_in[4];
    const float* Wk    = (const float*)d_in[5];
    const float* Wv    = (const float*)d_in[6];
    const float* bv    = (const float*)d_in[7];
    const float* Wa    = (const float*)d_in[8];
    const float* ba    = (const float*)d_in[9];
    const float* Wb    = (const float*)d_in[10];
    const float* bb    = (const float*)d_in[11];
    const float* Wp    = (const float*)d_in[12];
    const float* bp    = (const float*)d_in[13];
    const float* alpha = (const float*)d_in[14];
    const float* beta  = (const float*)d_in[15];

    u_kernel<<<dim3(64, N_), 256>>>(R, t);
    proj_kernel<<<dim3(16, 21), 256>>>(x, Wq, Wk, Wv, bv, Wa, ba, Wb, bb);
    st_kernel<<<dim3(8, 8, N_*H_), 256>>>();
    attn_p_kernel<<<dim3(16, H_, N_), 256>>>(R, t, alpha, beta);
    cudaFuncSetAttribute(pv_kernel, cudaFuncAttributeMaxDynamicSharedMemorySize, PV_SMEM);
    pv_kernel<<<dim3(8, H_, N_), 256, PV_SMEM>>>();
    out_kernel<<<dim3(128), 128>>>(Wp, bp, (float*)d_out);
}

// round 12
// speedup vs baseline: 1.1742x; 1.1742x over previous
#include <cuda_runtime.h>
#include <math.h>

#define N_    2
#define L_    512
#define H_    24
#define QK_   16
#define V_    16
#define HID_  128
#define CH_   504
#define EPS_  1e-6f
#define KPAD  20

// ---------------- scratch ----------------
__device__ float  g_q [N_*L_*H_*QK_];
__device__ float  g_kT[N_*H_*QK_*L_];
__device__ float  g_vT[N_*H_*V_ *L_];
__device__ float  g_a [N_*H_*L_*3];
__device__ float  g_b [N_*H_*L_*3];
__device__ float  g_cc[N_*L_*CH_];
__device__ float  g_uw[(size_t)N_*L_*L_];      // |R_i^T t_j|^2   2MB
__device__ float  g_st[(size_t)N_*H_*L_*L_];   // c1*q.k + bias  50MB

__device__ __forceinline__ float rsqrt_fast(float x) {
    float r; asm("rsqrt.approx.f32 %0,%1;" : "=f"(r) : "f"(x)); return r;
}
__device__ __forceinline__ float ex2_fast(float x) {
    float r; asm("ex2.approx.f32 %0,%1;" : "=f"(r) : "f"(x)); return r;
}
__device__ __forceinline__ float acos_fast(float x) {
    float ax = fminf(fabsf(x), 1.0f);
    float s; asm("sqrt.approx.f32 %0,%1;" : "=f"(s) : "f"(1.0f - ax));
    float p = fmaf(ax, -0.0187293f, 0.0742610f);
    p = fmaf(ax, p, -0.2121144f);
    p = fmaf(ax, p, 1.5707288f);
    float r = s * p;
    return x < 0.f ? 3.14159265359f - r : r;
}

// ================= kernel A: fused projections (proven ~22us) =================
#define PJS 68

__global__ void __launch_bounds__(256) proj_kernel(
    const float* __restrict__ x,
    const float* __restrict__ Wq, const float* __restrict__ Wk,
    const float* __restrict__ Wv, const float* __restrict__ bv,
    const float* __restrict__ Wa, const float* __restrict__ ba,
    const float* __restrict__ Wb, const float* __restrict__ bb)
{
    __shared__ float xs[32*PJS];
    __shared__ float ws[32*PJS];

    const int tid = threadIdx.x;
    const int rt  = blockIdx.x;
    const int ct  = blockIdx.y;
    const int tx = tid & 15;
    const int ty = tid >> 4;

    float acc[4][4];
    #pragma unroll
    for (int r = 0; r < 4; r++)
        #pragma unroll
        for (int c = 0; c < 4; c++) acc[r][c] = 0.f;

    #pragma unroll 1
    for (int chunk = 0; chunk < 4; chunk++) {
        __syncthreads();
        #pragma unroll
        for (int it = 0; it < 2; it++) {
            const int idx = it*256 + tid;
            const int kq = idx & 7;
            const int m  = idx >> 3;
            const float4 v = *(const float4*)(x + (size_t)(rt*64 + m)*HID_ + chunk*32 + kq*4);
            xs[(kq*4+0)*PJS + m] = v.x;
            xs[(kq*4+1)*PJS + m] = v.y;
            xs[(kq*4+2)*PJS + m] = v.z;
            xs[(kq*4+3)*PJS + m] = v.w;
        }
        #pragma unroll
        for (int it = 0; it < 2; it++) {
            const int idx = it*256 + tid;
            const int kq = idx & 7;
            const int cl = idx >> 3;
            const int c  = min(ct*64 + cl, 1295);
            const float* wrow;
            if      (c <  384) wrow = Wq + (size_t)c*HID_;
            else if (c <  768) wrow = Wk + (size_t)(c- 384)*HID_;
            else if (c < 1152) wrow = Wv + (size_t)(c- 768)*HID_;
            else if (c < 1224) wrow = Wa + (size_t)(c-1152)*HID_;
            else               wrow = Wb + (size_t)(c-1224)*HID_;
            const float4 v = *(const float4*)(wrow + chunk*32 + kq*4);
            ws[(kq*4+0)*PJS + cl] = v.x;
            ws[(kq*4+1)*PJS + cl] = v.y;
            ws[(kq*4+2)*PJS + cl] = v.z;
            ws[(kq*4+3)*PJS + cl] = v.w;
        }
        __syncthreads();

        #pragma unroll
        for (int k = 0; k < 32; k++) {
            const float4 xv = *(const float4*)(xs + k*PJS + tx*4);
            const float4 wv = *(const float4*)(ws + k*PJS + ty*4);
            const float xa[4] = {xv.x, xv.y, xv.z, xv.w};
            const float wa[4] = {wv.x, wv.y, wv.z, wv.w};
            #pragma unroll
            for (int r = 0; r < 4; r++)
                #pragma unroll
                for (int c = 0; c < 4; c++)
                    acc[r][c] = fmaf(xa[r], wa[c], acc[r][c]);
        }
    }

    #pragma unroll
    for (int r = 0; r < 4; r++) {
        const int gi = rt*64 + tx*4 + r;
        const int n = gi >> 9, i = gi & 511;
        #pragma unroll
        for (int cv = 0; cv < 4; cv++) {
            const int c = ct*64 + ty*4 + cv;
            if (c >= 1296) continue;
            float val = acc[r][cv];
            if (c < 384) {
                g_q[(size_t)gi*384 + c] = val;
            } else if (c < 768) {
                int cc = c - 384; int h = cc >> 4, d = cc & 15;
                g_kT[((size_t)(n*H_ + h)*QK_ + d)*L_ + i] = val;
            } else if (c < 1152) {
                int cc = c - 768; int h = cc >> 4, d = cc & 15;
                g_vT[((size_t)(n*H_ + h)*V_ + d)*L_ + i] = val + bv[cc];
            } else if (c < 1224) {
                int cc = c - 1152; int h = cc/3, xx = cc - h*3;
                g_a[((size_t)(n*H_ + h)*L_ + i)*3 + xx] = val + ba[cc];
            } else {
                int cc = c - 1224; int h = cc/3, xx = cc - h*3;
                g_b[((size_t)(n*H_ + h)*L_ + i)*3 + xx] = val + bb[cc];
            }
        }
    }
}

// ================= kernel U: uw = |R_i^T t_j|^2 =================
__global__ void __launch_bounds__(256) u_kernel(
    const float* __restrict__ Rm, const float* __restrict__ t)
{
    __shared__ float4 ts4[L_];
    const int tid = threadIdx.x;
    const int n = blockIdx.y;
    const int i = blockIdx.x*8 + (tid >> 5);
    const int lane = tid & 31;

    for (int j = tid; j < L_; j += 256) {
        const float* tp = t + (size_t)(n*L_ + j)*3;
        ts4[j] = make_float4(tp[0], tp[1], tp[2], 0.f);
    }
    __syncthreads();

    const float* Rp = Rm + (size_t)(n*L_ + i)*9;
    const float R00=Rp[0],R01=Rp[1],R02=Rp[2],
                R10=Rp[3],R11=Rp[4],R12=Rp[5],
                R20=Rp[6],R21=Rp[7],R22=Rp[8];

    float* up = g_uw + (size_t)(n*L_ + i)*L_;
    #pragma unroll 2
    for (int it = 0; it < 16; it++) {
        const int j = it*32 + lane;
        const float4 tj = ts4[j];
        const float ux = R00*tj.x + R10*tj.y + R20*tj.z;
        const float uy = R01*tj.x + R11*tj.y + R21*tj.z;
        const float uz = R02*tj.x + R12*tj.y + R22*tj.z;
        up[j] = fmaf(ux,ux, fmaf(uy,uy, uz*uz));
    }
}

// ================= kernel S: st = c1*(q.k) + bias =================
__global__ void __launch_bounds__(256) st_kernel()
{
    __shared__ float qs[16*68];
    __shared__ float ksm[16*64];

    const int tid = threadIdx.x;
    const int i0 = blockIdx.x * 64;
    const int j0 = blockIdx.y * 64;
    const int nh = blockIdx.z;
    const int n = nh / H_, h = nh - n*H_;

    {
        const int il = tid >> 2, dq = tid & 3;
        const float4 v = *(const float4*)(g_q + (size_t)(n*L_ + i0 + il)*384 + h*16 + dq*4);
        qs[(dq*4+0)*68 + il] = v.x;
        qs[(dq*4+1)*68 + il] = v.y;
        qs[(dq*4+2)*68 + il] = v.z;
        qs[(dq*4+3)*68 + il] = v.w;
    }
    {
        const int dk = tid >> 4, j4 = tid & 15;
        const float4 v = *(const float4*)(g_kT + ((size_t)nh*16 + dk)*L_ + j0 + j4*4);
        *(float4*)(ksm + dk*64 + j4*4) = v;
    }
    __syncthreads();

    const int tx = tid & 15;
    const int ty = tid >> 4;

    float acc[4][4];
    #pragma unroll
    for (int r = 0; r < 4; r++)
        #pragma unroll
        for (int c = 0; c < 4; c++) acc[r][c] = 0.f;

    #pragma unroll
    for (int d = 0; d < 16; d++) {
        const float4 qv = *(const float4*)(qs + d*68 + ty*4);
        const float4 kv = *(const float4*)(ksm + d*64 + tx*4);
        const float qa[4] = {qv.x, qv.y, qv.z, qv.w};
        const float ka[4] = {kv.x, kv.y, kv.z, kv.w};
        #pragma unroll
        for (int r = 0; r < 4; r++)
            #pragma unroll
            for (int c = 0; c < 4; c++)
                acc[r][c] = fmaf(qa[r], ka[c], acc[r][c]);
    }

    const float C1 = 0.70710678118f * 0.25f * 1.44269504089f;
    const float BIAS = -4.0f * 1.44269504089f;
    #pragma unroll
    for (int r = 0; r < 4; r++) {
        const int i = i0 + ty*4 + r;
        float4 o;
        o.x = fmaf(C1, acc[r][0], BIAS);
        o.y = fmaf(C1, acc[r][1], BIAS);
        o.z = fmaf(C1, acc[r][2], BIAS);
        o.w = fmaf(C1, acc[r][3], BIAS);
        *(float4*)(g_st + ((size_t)nh*L_ + i)*L_ + j0 + tx*4) = o;
    }
}

// ================= kernel B: ray attention (t-based, 2 rows/warp) =================
// rr  = uw - 2 t.(R c) + |c|^2 ;  r.a' = t.(R a') - c.a'
// sum(p r) = R^T (sum p t) - s c  (fixed after loop)
#define ATTN_SMEM ((L_*KPAD + 4*L_)*4)   // vs + ts4 = 49152 B

__global__ void __launch_bounds__(256, 2) attn_kernel(
    const float* __restrict__ Rm, const float* __restrict__ t,
    const float* __restrict__ alpha, const float* __restrict__ beta)
{
    extern __shared__ float sm[];
    float*  vs  = sm;                     // [512][20]
    float4* ts4 = (float4*)(sm + L_*KPAD);

    const int tid = threadIdx.x;
    const int n = blockIdx.z, h = blockIdx.y;
    const int i0 = blockIdx.x * 64;

    const float* vb = g_vT + (size_t)(n*H_ + h)*V_*L_;
    for (int idx = tid; idx < QK_*L_; idx += 256) {
        int d = idx >> 9, j = idx & 511;
        vs[j*KPAD + d] = vb[idx];
    }
    for (int j = tid; j < L_; j += 256) {
        const float* tp = t + (size_t)(n*L_ + j)*3;
        ts4[j] = make_float4(tp[0], tp[1], tp[2], 0.f);
    }
    __syncthreads();

    const float LOG2E = 1.44269504089f;
    const float al = log1pf(expf(alpha[h])) * 0.70710678118f * LOG2E;
    const float be = log1pf(expf(beta[h]))  * 0.70710678118f * LOG2E;
    const int warp = tid >> 5, lane = tid & 31;

    #pragma unroll 1
    for (int pass = 0; pass < 4; pass++) {
        const int iA = i0 + warp*8 + pass*2;
        const int iB = iA + 1;

        // ---- per-row prologues ----
        float w1xA,w1yA,w1zA, w2xA,w2yA,w2zA, cwA, caA, cA0,cA1,cA2;
        float w1xB,w1yB,w1zB, w2xB,w2yB,w2zB, cwB, caB, cB0,cB1,cB2;
        {
            const float* Rp = Rm + (size_t)(n*L_ + iA)*9;
            const float R00=Rp[0],R01=Rp[1],R02=Rp[2],
                        R10=Rp[3],R11=Rp[4],R12=Rp[5],
                        R20=Rp[6],R21=Rp[7],R22=Rp[8];
            const float4 ti = ts4[iA];
            const float* bp_ = g_b + ((size_t)(n*H_ + h)*L_ + iA)*3;
            cA0 = R00*ti.x + R10*ti.y + R20*ti.z + bp_[0];
            cA1 = R01*ti.x + R11*ti.y + R21*ti.z + bp_[1];
            cA2 = R02*ti.x + R12*ti.y + R22*ti.z + bp_[2];
            cwA = fmaf(cA0,cA0, fmaf(cA1,cA1, cA2*cA2));
            const float* ap = g_a + ((size_t)(n*H_ + h)*L_ + iA)*3;
            float a0=ap[0], a1=ap[1], a2=ap[2];
            const float inv = 1.0f/(sqrtf(a0*a0+a1*a1+a2*a2) + EPS_);
            a0 *= inv; a1 *= inv; a2 *= inv;
            caA = fmaf(cA0,a0, fmaf(cA1,a1, cA2*a2));
            w1xA = -2.f*(R00*cA0 + R01*cA1 + R02*cA2);
            w1yA = -2.f*(R10*cA0 + R11*cA1 + R12*cA2);
            w1zA = -2.f*(R20*cA0 + R21*cA1 + R22*cA2);
            w2xA = R00*a0 + R01*a1 + R02*a2;
            w2yA = R10*a0 + R11*a1 + R12*a2;
            w2zA = R20*a0 + R21*a1 + R22*a2;
        }
        {
            const float* Rp = Rm + (size_t)(n*L_ + iB)*9;
            const float R00=Rp[0],R01=Rp[1],R02=Rp[2],
                        R10=Rp[3],R11=Rp[4],R12=Rp[5],
                        R20=Rp[6],R21=Rp[7],R22=Rp[8];
            const float4 ti = ts4[iB];
            const float* bp_ = g_b + ((size_t)(n*H_ + h)*L_ + iB)*3;
            cB0 = R00*ti.x + R10*ti.y + R20*ti.z + bp_[0];
            cB1 = R01*ti.x + R11*ti.y + R21*ti.z + bp_[1];
            cB2 = R02*ti.x + R12*ti.y + R22*ti.z + bp_[2];
            cwB = fmaf(cB0,cB0, fmaf(cB1,cB1, cB2*cB2));
            const float* ap = g_a + ((size_t)(n*H_ + h)*L_ + iB)*3;
            float a0=ap[0], a1=ap[1], a2=ap[2];
            const float inv = 1.0f/(sqrtf(a0*a0+a1*a1+a2*a2) + EPS_);
            a0 *= inv; a1 *= inv; a2 *= inv;
            caB = fmaf(cB0,a0, fmaf(cB1,a1, cB2*a2));
            w1xB = -2.f*(R00*cB0 + R01*cB1 + R02*cB2);
            w1yB = -2.f*(R10*cB0 + R11*cB1 + R12*cB2);
            w1zB = -2.f*(R20*cB0 + R21*cB1 + R22*cB2);
            w2xB = R00*a0 + R01*a1 + R02*a2;
            w2yB = R10*a0 + R11*a1 + R12*a2;
            w2zB = R20*a0 + R21*a1 + R22*a2;
        }

        const float* uwA = g_uw + (size_t)(n*L_ + iA)*L_;
        const float* uwB = g_uw + (size_t)(n*L_ + iB)*L_;
        const float* stA = g_st + ((size_t)(n*H_ + h)*L_ + iA)*L_;
        const float* stB = g_st + ((size_t)(n*H_ + h)*L_ + iB)*L_;

        float sA=0.f, ptA0=0.f, ptA1=0.f, ptA2=0.f, pthA=0.f;
        float sB=0.f, ptB0=0.f, ptB1=0.f, ptB2=0.f, pthB=0.f;
        float avA[16], avB[16];
        #pragma unroll
        for (int d = 0; d < 16; d++) { avA[d]=0.f; avB[d]=0.f; }

        #pragma unroll 2
        for (int it = 0; it < 16; it++) {
            const int j = it*32 + lane;
            const float4 tj = ts4[j];

            // row A
            {
                const float uw = __ldg(uwA + j);
                const float st = __ldg(stA + j);
                float rr = fmaf(w1xA,tj.x, fmaf(w1yA,tj.y, fmaf(w1zA,tj.z, uw + cwA)));
                rr = fmaxf(rr, 1e-24f);
                const float ir = rsqrt_fast(rr);
                const float rs = rr * ir;
                const float rda = fmaf(w2xA,tj.x, fmaf(w2yA,tj.y, fmaf(w2zA,tj.z, -caA)));
                const float th = acos_fast(rda * ir);
                float arg = fmaf(-al, rs, fmaf(-be, th, st));
                if (j == iA) arg = -150.f;
                const float p = ex2_fast(arg);
                sA += p;
                ptA0 = fmaf(p, tj.x, ptA0);
                ptA1 = fmaf(p, tj.y, ptA1);
                ptA2 = fmaf(p, tj.z, ptA2);
                pthA = fmaf(p, th,  pthA);
                const float4* vj = (const float4*)(vs + j*KPAD);
                const float4 v0 = vj[0], v1 = vj[1], v2 = vj[2], v3 = vj[3];
                avA[0] =fmaf(p,v0.x,avA[0]);  avA[1] =fmaf(p,v0.y,avA[1]);  avA[2] =fmaf(p,v0.z,avA[2]);  avA[3] =fmaf(p,v0.w,avA[3]);
                avA[4] =fmaf(p,v1.x,avA[4]);  avA[5] =fmaf(p,v1.y,avA[5]);  avA[6] =fmaf(p,v1.z,avA[6]);  avA[7] =fmaf(p,v1.w,avA[7]);
                avA[8] =fmaf(p,v2.x,avA[8]);  avA[9] =fmaf(p,v2.y,avA[9]);  avA[10]=fmaf(p,v2.z,avA[10]); avA[11]=fmaf(p,v2.w,avA[11]);
                avA[12]=fmaf(p,v3.x,avA[12]); avA[13]=fmaf(p,v3.y,avA[13]); avA[14]=fmaf(p,v3.z,avA[14]); avA[15]=fmaf(p,v3.w,avA[15]);
                // row B (reuses tj and the same v registers)
                const float uwb = __ldg(uwB + j);
                const float stb = __ldg(stB + j);
                float rrb = fmaf(w1xB,tj.x, fmaf(w1yB,tj.y, fmaf(w1zB,tj.z, uwb + cwB)));
                rrb = fmaxf(rrb, 1e-24f);
                const float irb = rsqrt_fast(rrb);
                const float rsb = rrb * irb;
                const float rdab = fmaf(w2xB,tj.x, fmaf(w2yB,tj.y, fmaf(w2zB,tj.z, -caB)));
                const float thb = acos_fast(rdab * irb);
                float argb = fmaf(-al, rsb, fmaf(-be, thb, stb));
                if (j == iB) argb = -150.f;
                const float pb = ex2_fast(argb);
                sB += pb;
                ptB0 = fmaf(pb, tj.x, ptB0);
                ptB1 = fmaf(pb, tj.y, ptB1);
                ptB2 = fmaf(pb, tj.z, ptB2);
                pthB = fmaf(pb, thb, pthB);
                avB[0] =fmaf(pb,v0.x,avB[0]);  avB[1] =fmaf(pb,v0.y,avB[1]);  avB[2] =fmaf(pb,v0.z,avB[2]);  avB[3] =fmaf(pb,v0.w,avB[3]);
                avB[4] =fmaf(pb,v1.x,avB[4]);  avB[5] =fmaf(pb,v1.y,avB[5]);  avB[6] =fmaf(pb,v1.z,avB[6]);  avB[7] =fmaf(pb,v1.w,avB[7]);
                avB[8] =fmaf(pb,v2.x,avB[8]);  avB[9] =fmaf(pb,v2.y,avB[9]);  avB[10]=fmaf(pb,v2.z,avB[10]); avB[11]=fmaf(pb,v2.w,avB[11]);
                avB[12]=fmaf(pb,v3.x,avB[12]); avB[13]=fmaf(pb,v3.y,avB[13]); avB[14]=fmaf(pb,v3.z,avB[14]); avB[15]=fmaf(pb,v3.w,avB[15]);
            }
        }

        // ---- reductions + stores (per row) ----
        #pragma unroll
        for (int r = 0; r < 2; r++) {
            float* av = (r == 0) ? avA : avB;
            float s   = (r == 0) ? sA   : sB;
            float pt0 = (r == 0) ? ptA0 : ptB0;
            float pt1 = (r == 0) ? ptA1 : ptB1;
            float pt2 = (r == 0) ? ptA2 : ptB2;
            float pth = (r == 0) ? pthA : pthB;
            const int i = (r == 0) ? iA : iB;
            const float c0 = (r == 0) ? cA0 : cB0;
            const float c1 = (r == 0) ? cA1 : cB1;
            const float c2 = (r == 0) ? cA2 : cB2;

            #pragma unroll
            for (int k = 0; k < 4; k++) {
                const int half = 8 >> k;
                const bool up = (lane >> k) & 1;
                #pragma unroll
                for (int t2 = 0; t2 < half; t2++) {
                    float send = up ? av[t2] : av[t2 + half];
                    float recv = __shfl_xor_sync(0xffffffffu, send, 1 << k);
                    av[t2] = (up ? av[t2 + half] : av[t2]) + recv;
                }
            }
            av[0] += __shfl_xor_sync(0xffffffffu, av[0], 16);

            #pragma unroll
            for (int off = 16; off > 0; off >>= 1) {
                s   += __shfl_xor_sync(0xffffffffu, s,   off);
                pt0 += __shfl_xor_sync(0xffffffffu, pt0, off);
                pt1 += __shfl_xor_sync(0xffffffffu, pt1, off);
                pt2 += __shfl_xor_sync(0xffffffffu, pt2, off);
                pth += __shfl_xor_sync(0xffffffffu, pth, off);
            }
            const float inv = 1.0f / s;
            float* cc = g_cc + (size_t)(n*L_ + i)*CH_;
            if (lane < 16) {
                const int d = (int)(__brev((unsigned)lane) >> 28);
                cc[h*16 + d] = av[0] * inv;
            }
            if (lane == 0) {
                const float* Rp = Rm + (size_t)(n*L_ + i)*9;
                const float ra0 = (Rp[0]*pt0 + Rp[3]*pt1 + Rp[6]*pt2)*inv - c0;
                const float ra1 = (Rp[1]*pt0 + Rp[4]*pt1 + Rp[7]*pt2)*inv - c1;
                const float ra2 = (Rp[2]*pt0 + Rp[5]*pt1 + Rp[8]*pt2)*inv - c2;
                cc[384 + h*3 + 0] = ra0;
                cc[384 + h*3 + 1] = ra1;
                cc[384 + h*3 + 2] = ra2;
                cc[456 + h] = sqrtf(ra0*ra0 + ra1*ra1 + ra2*ra2);
                cc[480 + h] = pth*inv;
            }
        }
    }
}

// ================= kernel C: output projection =================
__global__ void out_kernel(const float* __restrict__ Wp, const float* __restrict__ bp,
                           float* __restrict__ out)
{
    __shared__ __align__(16) float cs[8*CH_];
    const int tid = threadIdx.x;
    const int r0 = blockIdx.x * 8;

    for (int idx = tid; idx < 8*CH_; idx += 128)
        cs[idx] = g_cc[(size_t)r0*CH_ + idx];
    __syncthreads();

    float acc[8];
    #pragma unroll
    for (int r = 0; r < 8; r++) acc[r] = 0.f;

    const float4* w4 = (const float4*)(Wp + (size_t)tid*CH_);
    #pragma unroll 2
    for (int k4 = 0; k4 < CH_/4; k4++) {
        const float4 w = w4[k4];
        #pragma unroll
        for (int r = 0; r < 8; r++) {
            const float4 cv = ((const float4*)(cs + r*CH_))[k4];
            acc[r] += cv.x*w.x + cv.y*w.y + cv.z*w.z + cv.w*w.w;
        }
    }
    const float bbv = bp[tid];
    #pragma unroll
    for (int r = 0; r < 8; r++)
        out[(size_t)(r0 + r)*HID_ + tid] = acc[r] + bbv;
}

// ---------------- launch ----------------
extern "C" void kernel_launch(void* const* d_in, const int* in_sizes, int n_in,
                              void* d_out, int out_size)
{
    const float* x     = (const float*)d_in[0];
    const float* R     = (const float*)d_in[1];
    const float* t     = (const float*)d_in[2];
    const float* Wq    = (const float*)d_in[4];
    const float* Wk    = (const float*)d_in[5];
    const float* Wv    = (const float*)d_in[6];
    const float* bv    = (const float*)d_in[7];
    const float* Wa    = (const float*)d_in[8];
    const float* ba    = (const float*)d_in[9];
    const float* Wb    = (const float*)d_in[10];
    const float* bb    = (const float*)d_in[11];
    const float* Wp    = (const float*)d_in[12];
    const float* bp    = (const float*)d_in[13];
    const float* alpha = (const float*)d_in[14];
    const float* beta  = (const float*)d_in[15];

    u_kernel<<<dim3(64, N_), 256>>>(R, t);
    proj_kernel<<<dim3(16, 21), 256>>>(x, Wq, Wk, Wv, bv, Wa, ba, Wb, bb);
    st_kernel<<<dim3(8, 8, N_*H_), 256>>>();
    cudaFuncSetAttribute(attn_kernel, cudaFuncAttributeMaxDynamicSharedMemorySize, ATTN_SMEM);
    attn_kernel<<<dim3(8, H_, N_), 256, ATTN_SMEM>>>(R, t, alpha, beta);
    out_kernel<<<dim3(128), 128>>>(Wp, bp, (float*)d_out);
}

// round 13
// speedup vs baseline: 1.2236x; 1.0421x over previous
#include <cuda_runtime.h>
#include <math.h>

#define N_    2
#define L_    512
#define H_    24
#define QK_   16
#define V_    16
#define HID_  128
#define CH_   504
#define EPS_  1e-6f
#define KPAD  20

// ---------------- scratch ----------------
__device__ float  g_q [N_*L_*H_*QK_];
__device__ float  g_kT[N_*H_*QK_*L_];
__device__ float  g_vT[N_*H_*V_ *L_];
__device__ float  g_a [N_*H_*L_*3];
__device__ float  g_b [N_*H_*L_*3];
__device__ float  g_cc[N_*L_*CH_];
__device__ float  g_uw[(size_t)N_*L_*L_];      // |R_i^T t_j|^2   2MB
__device__ float  g_st[(size_t)N_*H_*L_*L_];   // c1*q.k + bias  50MB

__device__ __forceinline__ float rsqrt_fast(float x) {
    float r; asm("rsqrt.approx.f32 %0,%1;" : "=f"(r) : "f"(x)); return r;
}
__device__ __forceinline__ float ex2_fast(float x) {
    float r; asm("ex2.approx.f32 %0,%1;" : "=f"(r) : "f"(x)); return r;
}
__device__ __forceinline__ float acos_fast(float x) {
    float ax = fminf(fabsf(x), 1.0f);
    float s; asm("sqrt.approx.f32 %0,%1;" : "=f"(s) : "f"(1.0f - ax));
    float p = fmaf(ax, -0.0187293f, 0.0742610f);
    p = fmaf(ax, p, -0.2121144f);
    p = fmaf(ax, p, 1.5707288f);
    float r = s * p;
    return x < 0.f ? 3.14159265359f - r : r;
}

// ================= kernel A: fused projections (proven ~22us) =================
#define PJS 68

__global__ void __launch_bounds__(256) proj_kernel(
    const float* __restrict__ x,
    const float* __restrict__ Wq, const float* __restrict__ Wk,
    const float* __restrict__ Wv, const float* __restrict__ bv,
    const float* __restrict__ Wa, const float* __restrict__ ba,
    const float* __restrict__ Wb, const float* __restrict__ bb)
{
    __shared__ float xs[32*PJS];
    __shared__ float ws[32*PJS];

    const int tid = threadIdx.x;
    const int rt  = blockIdx.x;
    const int ct  = blockIdx.y;
    const int tx = tid & 15;
    const int ty = tid >> 4;

    float acc[4][4];
    #pragma unroll
    for (int r = 0; r < 4; r++)
        #pragma unroll
        for (int c = 0; c < 4; c++) acc[r][c] = 0.f;

    #pragma unroll 1
    for (int chunk = 0; chunk < 4; chunk++) {
        __syncthreads();
        #pragma unroll
        for (int it = 0; it < 2; it++) {
            const int idx = it*256 + tid;
            const int kq = idx & 7;
            const int m  = idx >> 3;
            const float4 v = *(const float4*)(x + (size_t)(rt*64 + m)*HID_ + chunk*32 + kq*4);
            xs[(kq*4+0)*PJS + m] = v.x;
            xs[(kq*4+1)*PJS + m] = v.y;
            xs[(kq*4+2)*PJS + m] = v.z;
            xs[(kq*4+3)*PJS + m] = v.w;
        }
        #pragma unroll
        for (int it = 0; it < 2; it++) {
            const int idx = it*256 + tid;
            const int kq = idx & 7;
            const int cl = idx >> 3;
            const int c  = min(ct*64 + cl, 1295);
            const float* wrow;
            if      (c <  384) wrow = Wq + (size_t)c*HID_;
            else if (c <  768) wrow = Wk + (size_t)(c- 384)*HID_;
            else if (c < 1152) wrow = Wv + (size_t)(c- 768)*HID_;
            else if (c < 1224) wrow = Wa + (size_t)(c-1152)*HID_;
            else               wrow = Wb + (size_t)(c-1224)*HID_;
            const float4 v = *(const float4*)(wrow + chunk*32 + kq*4);
            ws[(kq*4+0)*PJS + cl] = v.x;
            ws[(kq*4+1)*PJS + cl] = v.y;
            ws[(kq*4+2)*PJS + cl] = v.z;
            ws[(kq*4+3)*PJS + cl] = v.w;
        }
        __syncthreads();

        #pragma unroll
        for (int k = 0; k < 32; k++) {
            const float4 xv = *(const float4*)(xs + k*PJS + tx*4);
            const float4 wv = *(const float4*)(ws + k*PJS + ty*4);
            const float xa[4] = {xv.x, xv.y, xv.z, xv.w};
            const float wa[4] = {wv.x, wv.y, wv.z, wv.w};
            #pragma unroll
            for (int r = 0; r < 4; r++)
                #pragma unroll
                for (int c = 0; c < 4; c++)
                    acc[r][c] = fmaf(xa[r], wa[c], acc[r][c]);
        }
    }

    #pragma unroll
    for (int r = 0; r < 4; r++) {
        const int gi = rt*64 + tx*4 + r;
        const int n = gi >> 9, i = gi & 511;
        #pragma unroll
        for (int cv = 0; cv < 4; cv++) {
            const int c = ct*64 + ty*4 + cv;
            if (c >= 1296) continue;
            float val = acc[r][cv];
            if (c < 384) {
                g_q[(size_t)gi*384 + c] = val;
            } else if (c < 768) {
                int cc = c - 384; int h = cc >> 4, d = cc & 15;
                g_kT[((size_t)(n*H_ + h)*QK_ + d)*L_ + i] = val;
            } else if (c < 1152) {
                int cc = c - 768; int h = cc >> 4, d = cc & 15;
                g_vT[((size_t)(n*H_ + h)*V_ + d)*L_ + i] = val + bv[cc];
            } else if (c < 1224) {
                int cc = c - 1152; int h = cc/3, xx = cc - h*3;
                g_a[((size_t)(n*H_ + h)*L_ + i)*3 + xx] = val + ba[cc];
            } else {
                int cc = c - 1224; int h = cc/3, xx = cc - h*3;
                g_b[((size_t)(n*H_ + h)*L_ + i)*3 + xx] = val + bb[cc];
            }
        }
    }
}

// ================= kernel U: uw = |R_i^T t_j|^2 =================
__global__ void __launch_bounds__(256) u_kernel(
    const float* __restrict__ Rm, const float* __restrict__ t)
{
    __shared__ float4 ts4[L_];
    const int tid = threadIdx.x;
    const int n = blockIdx.y;
    const int i = blockIdx.x*8 + (tid >> 5);
    const int lane = tid & 31;

    for (int j = tid; j < L_; j += 256) {
        const float* tp = t + (size_t)(n*L_ + j)*3;
        ts4[j] = make_float4(tp[0], tp[1], tp[2], 0.f);
    }
    __syncthreads();

    const float* Rp = Rm + (size_t)(n*L_ + i)*9;
    const float R00=Rp[0],R01=Rp[1],R02=Rp[2],
                R10=Rp[3],R11=Rp[4],R12=Rp[5],
                R20=Rp[6],R21=Rp[7],R22=Rp[8];

    float* up = g_uw + (size_t)(n*L_ + i)*L_;
    #pragma unroll 2
    for (int it = 0; it < 16; it++) {
        const int j = it*32 + lane;
        const float4 tj = ts4[j];
        const float ux = R00*tj.x + R10*tj.y + R20*tj.z;
        const float uy = R01*tj.x + R11*tj.y + R21*tj.z;
        const float uz = R02*tj.x + R12*tj.y + R22*tj.z;
        up[j] = fmaf(ux,ux, fmaf(uy,uy, uz*uz));
    }
}

// ================= kernel S: st = c1*(q.k) + bias =================
__global__ void __launch_bounds__(256) st_kernel()
{
    __shared__ float qs[16*68];
    __shared__ float ksm[16*64];

    const int tid = threadIdx.x;
    const int i0 = blockIdx.x * 64;
    const int j0 = blockIdx.y * 64;
    const int nh = blockIdx.z;
    const int n = nh / H_, h = nh - n*H_;

    {
        const int il = tid >> 2, dq = tid & 3;
        const float4 v = *(const float4*)(g_q + (size_t)(n*L_ + i0 + il)*384 + h*16 + dq*4);
        qs[(dq*4+0)*68 + il] = v.x;
        qs[(dq*4+1)*68 + il] = v.y;
        qs[(dq*4+2)*68 + il] = v.z;
        qs[(dq*4+3)*68 + il] = v.w;
    }
    {
        const int dk = tid >> 4, j4 = tid & 15;
        const float4 v = *(const float4*)(g_kT + ((size_t)nh*16 + dk)*L_ + j0 + j4*4);
        *(float4*)(ksm + dk*64 + j4*4) = v;
    }
    __syncthreads();

    const int tx = tid & 15;
    const int ty = tid >> 4;

    float acc[4][4];
    #pragma unroll
    for (int r = 0; r < 4; r++)
        #pragma unroll
        for (int c = 0; c < 4; c++) acc[r][c] = 0.f;

    #pragma unroll
    for (int d = 0; d < 16; d++) {
        const float4 qv = *(const float4*)(qs + d*68 + ty*4);
        const float4 kv = *(const float4*)(ksm + d*64 + tx*4);
        const float qa[4] = {qv.x, qv.y, qv.z, qv.w};
        const float ka[4] = {kv.x, kv.y, kv.z, kv.w};
        #pragma unroll
        for (int r = 0; r < 4; r++)
            #pragma unroll
            for (int c = 0; c < 4; c++)
                acc[r][c] = fmaf(qa[r], ka[c], acc[r][c]);
    }

    const float C1 = 0.70710678118f * 0.25f * 1.44269504089f;
    const float BIAS = -4.0f * 1.44269504089f;
    #pragma unroll
    for (int r = 0; r < 4; r++) {
        const int i = i0 + ty*4 + r;
        float4 o;
        o.x = fmaf(C1, acc[r][0], BIAS);
        o.y = fmaf(C1, acc[r][1], BIAS);
        o.z = fmaf(C1, acc[r][2], BIAS);
        o.w = fmaf(C1, acc[r][3], BIAS);
        *(float4*)(g_st + ((size_t)nh*L_ + i)*L_ + j0 + tx*4) = o;
    }
}

// ================= kernel B: ray attention (R10 proven, wider grid) =================
// rr  = uw - 2 t.(R c) + |c|^2 ;  r.a' = t.(R a') - c.a'
// sum(p r) = R^T (sum p t) - s c  (fixed after loop)
#define ATTN_SMEM ((L_*KPAD + 4*L_)*4)   // vs + ts4 = 49152 B

__global__ void __launch_bounds__(256, 3) attn_kernel(
    const float* __restrict__ Rm, const float* __restrict__ t,
    const float* __restrict__ alpha, const float* __restrict__ beta)
{
    extern __shared__ float sm[];
    float*  vs  = sm;
    float4* ts4 = (float4*)(sm + L_*KPAD);

    const int tid = threadIdx.x;
    const int n = blockIdx.z, h = blockIdx.y;
    const int i0 = blockIdx.x * 32;

    const float* vb = g_vT + (size_t)(n*H_ + h)*V_*L_;
    for (int idx = tid; idx < QK_*L_; idx += 256) {
        int d = idx >> 9, j = idx & 511;
        vs[j*KPAD + d] = vb[idx];
    }
    for (int j = tid; j < L_; j += 256) {
        const float* tp = t + (size_t)(n*L_ + j)*3;
        ts4[j] = make_float4(tp[0], tp[1], tp[2], 0.f);
    }
    __syncthreads();

    const float LOG2E = 1.44269504089f;
    const float al = log1pf(expf(alpha[h])) * 0.70710678118f * LOG2E;
    const float be = log1pf(expf(beta[h]))  * 0.70710678118f * LOG2E;
    const int warp = tid >> 5, lane = tid & 31;

    #pragma unroll 1
    for (int pass = 0; pass < 4; pass++) {
        const int i = i0 + warp*4 + pass;

        float w1x, w1y, w1z, w2x, w2y, w2z, cw, ca, c0, c1, c2;
        {
            const float* Rp = Rm + (size_t)(n*L_ + i)*9;
            const float R00=Rp[0],R01=Rp[1],R02=Rp[2],
                        R10=Rp[3],R11=Rp[4],R12=Rp[5],
                        R20=Rp[6],R21=Rp[7],R22=Rp[8];
            const float4 ti = ts4[i];
            const float* bp_ = g_b + ((size_t)(n*H_ + h)*L_ + i)*3;
            c0 = R00*ti.x + R10*ti.y + R20*ti.z + bp_[0];
            c1 = R01*ti.x + R11*ti.y + R21*ti.z + bp_[1];
            c2 = R02*ti.x + R12*ti.y + R22*ti.z + bp_[2];
            cw = fmaf(c0,c0, fmaf(c1,c1, c2*c2));
            const float* ap = g_a + ((size_t)(n*H_ + h)*L_ + i)*3;
            float a0=ap[0], a1=ap[1], a2=ap[2];
            const float inv = 1.0f/(sqrtf(a0*a0+a1*a1+a2*a2) + EPS_);
            a0 *= inv; a1 *= inv; a2 *= inv;
            ca = fmaf(c0,a0, fmaf(c1,a1, c2*a2));
            w1x = -2.f*(R00*c0 + R01*c1 + R02*c2);
            w1y = -2.f*(R10*c0 + R11*c1 + R12*c2);
            w1z = -2.f*(R20*c0 + R21*c1 + R22*c2);
            w2x = R00*a0 + R01*a1 + R02*a2;
            w2y = R10*a0 + R11*a1 + R12*a2;
            w2z = R20*a0 + R21*a1 + R22*a2;
        }

        const float* uwp = g_uw + (size_t)(n*L_ + i)*L_;
        const float* stp = g_st + ((size_t)(n*H_ + h)*L_ + i)*L_;

        float s=0.f, pt0=0.f, pt1=0.f, pt2=0.f, pth=0.f;
        float av[16];
        #pragma unroll
        for (int d = 0; d < 16; d++) av[d] = 0.f;

        #pragma unroll 2
        for (int it = 0; it < 16; it++) {
            const int j = it*32 + lane;
            const float uw = __ldg(uwp + j);
            const float st = __ldg(stp + j);
            const float4 tj = ts4[j];

            float rr = fmaf(w1x,tj.x, fmaf(w1y,tj.y, fmaf(w1z,tj.z, uw + cw)));
            rr = fmaxf(rr, 1e-24f);
            const float ir = rsqrt_fast(rr);
            const float rs = rr * ir;
            const float rda = fmaf(w2x,tj.x, fmaf(w2y,tj.y, fmaf(w2z,tj.z, -ca)));
            const float th = acos_fast(rda * ir);
            float arg = fmaf(-al, rs, fmaf(-be, th, st));
            if (j == i) arg = -150.f;
            const float p = ex2_fast(arg);

            s += p;
            pt0 = fmaf(p, tj.x, pt0);
            pt1 = fmaf(p, tj.y, pt1);
            pt2 = fmaf(p, tj.z, pt2);
            pth = fmaf(p, th,  pth);

            const float4* vj = (const float4*)(vs + j*KPAD);
            const float4 v0 = vj[0], v1 = vj[1], v2 = vj[2], v3 = vj[3];
            av[0] =fmaf(p,v0.x,av[0]);  av[1] =fmaf(p,v0.y,av[1]);  av[2] =fmaf(p,v0.z,av[2]);  av[3] =fmaf(p,v0.w,av[3]);
            av[4] =fmaf(p,v1.x,av[4]);  av[5] =fmaf(p,v1.y,av[5]);  av[6] =fmaf(p,v1.z,av[6]);  av[7] =fmaf(p,v1.w,av[7]);
            av[8] =fmaf(p,v2.x,av[8]);  av[9] =fmaf(p,v2.y,av[9]);  av[10]=fmaf(p,v2.z,av[10]); av[11]=fmaf(p,v2.w,av[11]);
            av[12]=fmaf(p,v3.x,av[12]); av[13]=fmaf(p,v3.y,av[13]); av[14]=fmaf(p,v3.z,av[14]); av[15]=fmaf(p,v3.w,av[15]);
        }

        #pragma unroll
        for (int k = 0; k < 4; k++) {
            const int half = 8 >> k;
            const bool up = (lane >> k) & 1;
            #pragma unroll
            for (int t2 = 0; t2 < half; t2++) {
                float send = up ? av[t2] : av[t2 + half];
                float recv = __shfl_xor_sync(0xffffffffu, send, 1 << k);
                av[t2] = (up ? av[t2 + half] : av[t2]) + recv;
            }
        }
        av[0] += __shfl_xor_sync(0xffffffffu, av[0], 16);

        #pragma unroll
        for (int off = 16; off > 0; off >>= 1) {
            s   += __shfl_xor_sync(0xffffffffu, s,   off);
            pt0 += __shfl_xor_sync(0xffffffffu, pt0, off);
            pt1 += __shfl_xor_sync(0xffffffffu, pt1, off);
            pt2 += __shfl_xor_sync(0xffffffffu, pt2, off);
            pth += __shfl_xor_sync(0xffffffffu, pth, off);
        }
        const float inv = 1.0f / s;
        float* cc = g_cc + (size_t)(n*L_ + i)*CH_;
        if (lane < 16) {
            const int d = (int)(__brev((unsigned)lane) >> 28);
            cc[h*16 + d] = av[0] * inv;
        }
        if (lane == 0) {
            const float* Rp = Rm + (size_t)(n*L_ + i)*9;
            const float ra0 = (Rp[0]*pt0 + Rp[3]*pt1 + Rp[6]*pt2)*inv - c0;
            const float ra1 = (Rp[1]*pt0 + Rp[4]*pt1 + Rp[7]*pt2)*inv - c1;
            const float ra2 = (Rp[2]*pt0 + Rp[5]*pt1 + Rp[8]*pt2)*inv - c2;
            cc[384 + h*3 + 0] = ra0;
            cc[384 + h*3 + 1] = ra1;
            cc[384 + h*3 + 2] = ra2;
            cc[456 + h] = sqrtf(ra0*ra0 + ra1*ra1 + ra2*ra2);
            cc[480 + h] = pth*inv;
        }
    }
}

// ================= kernel C: output projection (16 rows/block) =================
__global__ void __launch_bounds__(256) out_kernel(
    const float* __restrict__ Wp, const float* __restrict__ bp,
    float* __restrict__ out)
{
    __shared__ __align__(16) float cs[16*CH_];   // 32.25KB
    const int tid = threadIdx.x;
    const int r0 = blockIdx.x * 16;

    for (int idx = tid; idx < 16*CH_; idx += 256)
        cs[idx] = g_cc[(size_t)r0*CH_ + idx];
    __syncthreads();

    const int col = tid & 127;        // output column
    const int rh  = tid >> 7;         // row half: 0 -> rows 0-7, 1 -> rows 8-15

    float acc[8];
    #pragma unroll
    for (int r = 0; r < 8; r++) acc[r] = 0.f;

    const float4* w4 = (const float4*)(Wp + (size_t)col*CH_);
    const float* csb = cs + rh*8*CH_;
    #pragma unroll 2
    for (int k4 = 0; k4 < CH_/4; k4++) {
        const float4 w = w4[k4];
        #pragma unroll
        for (int r = 0; r < 8; r++) {
            const float4 cv = ((const float4*)(csb + r*CH_))[k4];
            acc[r] += cv.x*w.x + cv.y*w.y + cv.z*w.z + cv.w*w.w;
        }
    }
    const float bbv = bp[col];
    #pragma unroll
    for (int r = 0; r < 8; r++)
        out[(size_t)(r0 + rh*8 + r)*HID_ + col] = acc[r] + bbv;
}

// ---------------- launch ----------------
extern "C" void kernel_launch(void* const* d_in, const int* in_sizes, int n_in,
                              void* d_out, int out_size)
{
    const float* x     = (const float*)d_in[0];
    const float* R     = (const float*)d_in[1];
    const float* t     = (const float*)d_in[2];
    const float* Wq    = (const float*)d_in[4];
    const float* Wk    = (const float*)d_in[5];
    const float* Wv    = (const float*)d_in[6];
    const float* bv    = (const float*)d_in[7];
    const float* Wa    = (const float*)d_in[8];
    const float* ba    = (const float*)d_in[9];
    const float* Wb    = (const float*)d_in[10];
    const float* bb    = (const float*)d_in[11];
    const float* Wp    = (const float*)d_in[12];
    const float* bp    = (const float*)d_in[13];
    const float* alpha = (const float*)d_in[14];
    const float* beta  = (const float*)d_in[15];

    u_kernel<<<dim3(64, N_), 256>>>(R, t);
    proj_kernel<<<dim3(16, 21), 256>>>(x, Wq, Wk, Wv, bv, Wa, ba, Wb, bb);
    st_kernel<<<dim3(8, 8, N_*H_), 256>>>();
    cudaFuncSetAttribute(attn_kernel, cudaFuncAttributeMaxDynamicSharedMemorySize, ATTN_SMEM);
    attn_kernel<<<dim3(16, H_, N_), 256, ATTN_SMEM>>>(R, t, alpha, beta);
    out_kernel<<<dim3(64), 256>>>(Wp, bp, (float*)d_out);
}

// round 14
// speedup vs baseline: 1.2340x; 1.0084x over previous
#include <cuda_runtime.h>
#include <cuda_fp16.h>
#include <math.h>

#define N_    2
#define L_    512
#define H_    24
#define QK_   16
#define V_    16
#define HID_  128
#define CH_   504
#define EPS_  1e-6f
#define KPAD  20

// ---------------- scratch ----------------
__device__ float  g_q [N_*L_*H_*QK_];
__device__ float  g_kT[N_*H_*QK_*L_];
__device__ float  g_vT[N_*H_*V_ *L_];
__device__ float  g_a [N_*H_*L_*3];
__device__ float  g_b [N_*H_*L_*3];
__device__ float  g_cc[N_*L_*CH_];
__device__ float  g_uw[(size_t)N_*L_*L_];      // |R_i^T t_j|^2   2MB
__device__ __half g_st[(size_t)N_*H_*L_*L_];   // c1*q.k + bias  25MB (fp16)

__device__ __forceinline__ float rsqrt_fast(float x) {
    float r; asm("rsqrt.approx.f32 %0,%1;" : "=f"(r) : "f"(x)); return r;
}
__device__ __forceinline__ float ex2_fast(float x) {
    float r; asm("ex2.approx.f32 %0,%1;" : "=f"(r) : "f"(x)); return r;
}
__device__ __forceinline__ float acos_fast(float x) {
    float ax = fminf(fabsf(x), 1.0f);
    float s; asm("sqrt.approx.f32 %0,%1;" : "=f"(s) : "f"(1.0f - ax));
    float p = fmaf(ax, -0.0187293f, 0.0742610f);
    p = fmaf(ax, p, -0.2121144f);
    p = fmaf(ax, p, 1.5707288f);
    float r = s * p;
    return x < 0.f ? 3.14159265359f - r : r;
}

// ================= kernel A: fused projections (proven ~22us) =================
#define PJS 68

__global__ void __launch_bounds__(256) proj_kernel(
    const float* __restrict__ x,
    const float* __restrict__ Wq, const float* __restrict__ Wk,
    const float* __restrict__ Wv, const float* __restrict__ bv,
    const float* __restrict__ Wa, const float* __restrict__ ba,
    const float* __restrict__ Wb, const float* __restrict__ bb)
{
    __shared__ float xs[32*PJS];
    __shared__ float ws[32*PJS];

    const int tid = threadIdx.x;
    const int rt  = blockIdx.x;
    const int ct  = blockIdx.y;
    const int tx = tid & 15;
    const int ty = tid >> 4;

    float acc[4][4];
    #pragma unroll
    for (int r = 0; r < 4; r++)
        #pragma unroll
        for (int c = 0; c < 4; c++) acc[r][c] = 0.f;

    #pragma unroll 1
    for (int chunk = 0; chunk < 4; chunk++) {
        __syncthreads();
        #pragma unroll
        for (int it = 0; it < 2; it++) {
            const int idx = it*256 + tid;
            const int kq = idx & 7;
            const int m  = idx >> 3;
            const float4 v = *(const float4*)(x + (size_t)(rt*64 + m)*HID_ + chunk*32 + kq*4);
            xs[(kq*4+0)*PJS + m] = v.x;
            xs[(kq*4+1)*PJS + m] = v.y;
            xs[(kq*4+2)*PJS + m] = v.z;
            xs[(kq*4+3)*PJS + m] = v.w;
        }
        #pragma unroll
        for (int it = 0; it < 2; it++) {
            const int idx = it*256 + tid;
            const int kq = idx & 7;
            const int cl = idx >> 3;
            const int c  = min(ct*64 + cl, 1295);
            const float* wrow;
            if      (c <  384) wrow = Wq + (size_t)c*HID_;
            else if (c <  768) wrow = Wk + (size_t)(c- 384)*HID_;
            else if (c < 1152) wrow = Wv + (size_t)(c- 768)*HID_;
            else if (c < 1224) wrow = Wa + (size_t)(c-1152)*HID_;
            else               wrow = Wb + (size_t)(c-1224)*HID_;
            const float4 v = *(const float4*)(wrow + chunk*32 + kq*4);
            ws[(kq*4+0)*PJS + cl] = v.x;
            ws[(kq*4+1)*PJS + cl] = v.y;
            ws[(kq*4+2)*PJS + cl] = v.z;
            ws[(kq*4+3)*PJS + cl] = v.w;
        }
        __syncthreads();

        #pragma unroll
        for (int k = 0; k < 32; k++) {
            const float4 xv = *(const float4*)(xs + k*PJS + tx*4);
            const float4 wv = *(const float4*)(ws + k*PJS + ty*4);
            const float xa[4] = {xv.x, xv.y, xv.z, xv.w};
            const float wa[4] = {wv.x, wv.y, wv.z, wv.w};
            #pragma unroll
            for (int r = 0; r < 4; r++)
                #pragma unroll
                for (int c = 0; c < 4; c++)
                    acc[r][c] = fmaf(xa[r], wa[c], acc[r][c]);
        }
    }

    #pragma unroll
    for (int r = 0; r < 4; r++) {
        const int gi = rt*64 + tx*4 + r;
        const int n = gi >> 9, i = gi & 511;
        #pragma unroll
        for (int cv = 0; cv < 4; cv++) {
            const int c = ct*64 + ty*4 + cv;
            if (c >= 1296) continue;
            float val = acc[r][cv];
            if (c < 384) {
                g_q[(size_t)gi*384 + c] = val;
            } else if (c < 768) {
                int cc = c - 384; int h = cc >> 4, d = cc & 15;
                g_kT[((size_t)(n*H_ + h)*QK_ + d)*L_ + i] = val;
            } else if (c < 1152) {
                int cc = c - 768; int h = cc >> 4, d = cc & 15;
                g_vT[((size_t)(n*H_ + h)*V_ + d)*L_ + i] = val + bv[cc];
            } else if (c < 1224) {
                int cc = c - 1152; int h = cc/3, xx = cc - h*3;
                g_a[((size_t)(n*H_ + h)*L_ + i)*3 + xx] = val + ba[cc];
            } else {
                int cc = c - 1224; int h = cc/3, xx = cc - h*3;
                g_b[((size_t)(n*H_ + h)*L_ + i)*3 + xx] = val + bb[cc];
            }
        }
    }
}

// ================= kernel U: uw = |R_i^T t_j|^2 =================
__global__ void __launch_bounds__(256) u_kernel(
    const float* __restrict__ Rm, const float* __restrict__ t)
{
    __shared__ float4 ts4[L_];
    const int tid = threadIdx.x;
    const int n = blockIdx.y;
    const int i = blockIdx.x*8 + (tid >> 5);
    const int lane = tid & 31;

    for (int j = tid; j < L_; j += 256) {
        const float* tp = t + (size_t)(n*L_ + j)*3;
        ts4[j] = make_float4(tp[0], tp[1], tp[2], 0.f);
    }
    __syncthreads();

    const float* Rp = Rm + (size_t)(n*L_ + i)*9;
    const float R00=Rp[0],R01=Rp[1],R02=Rp[2],
                R10=Rp[3],R11=Rp[4],R12=Rp[5],
                R20=Rp[6],R21=Rp[7],R22=Rp[8];

    float* up = g_uw + (size_t)(n*L_ + i)*L_;
    #pragma unroll 2
    for (int it = 0; it < 16; it++) {
        const int j = it*32 + lane;
        const float4 tj = ts4[j];
        const float ux = R00*tj.x + R10*tj.y + R20*tj.z;
        const float uy = R01*tj.x + R11*tj.y + R21*tj.z;
        const float uz = R02*tj.x + R12*tj.y + R22*tj.z;
        up[j] = fmaf(ux,ux, fmaf(uy,uy, uz*uz));
    }
}

// ================= kernel S: st = c1*(q.k) + bias (fp16 out) =================
__global__ void __launch_bounds__(256) st_kernel()
{
    __shared__ float qs[16*68];
    __shared__ float ksm[16*64];

    const int tid = threadIdx.x;
    const int i0 = blockIdx.x * 64;
    const int j0 = blockIdx.y * 64;
    const int nh = blockIdx.z;
    const int n = nh / H_, h = nh - n*H_;

    {
        const int il = tid >> 2, dq = tid & 3;
        const float4 v = *(const float4*)(g_q + (size_t)(n*L_ + i0 + il)*384 + h*16 + dq*4);
        qs[(dq*4+0)*68 + il] = v.x;
        qs[(dq*4+1)*68 + il] = v.y;
        qs[(dq*4+2)*68 + il] = v.z;
        qs[(dq*4+3)*68 + il] = v.w;
    }
    {
        const int dk = tid >> 4, j4 = tid & 15;
        const float4 v = *(const float4*)(g_kT + ((size_t)nh*16 + dk)*L_ + j0 + j4*4);
        *(float4*)(ksm + dk*64 + j4*4) = v;
    }
    __syncthreads();

    const int tx = tid & 15;
    const int ty = tid >> 4;

    float acc[4][4];
    #pragma unroll
    for (int r = 0; r < 4; r++)
        #pragma unroll
        for (int c = 0; c < 4; c++) acc[r][c] = 0.f;

    #pragma unroll
    for (int d = 0; d < 16; d++) {
        const float4 qv = *(const float4*)(qs + d*68 + ty*4);
        const float4 kv = *(const float4*)(ksm + d*64 + tx*4);
        const float qa[4] = {qv.x, qv.y, qv.z, qv.w};
        const float ka[4] = {kv.x, kv.y, kv.z, kv.w};
        #pragma unroll
        for (int r = 0; r < 4; r++)
            #pragma unroll
            for (int c = 0; c < 4; c++)
                acc[r][c] = fmaf(qa[r], ka[c], acc[r][c]);
    }

    const float C1 = 0.70710678118f * 0.25f * 1.44269504089f;
    const float BIAS = -4.0f * 1.44269504089f;
    #pragma unroll
    for (int r = 0; r < 4; r++) {
        const int i = i0 + ty*4 + r;
        const float o0 = fmaf(C1, acc[r][0], BIAS);
        const float o1 = fmaf(C1, acc[r][1], BIAS);
        const float o2 = fmaf(C1, acc[r][2], BIAS);
        const float o3 = fmaf(C1, acc[r][3], BIAS);
        __half* dst = g_st + ((size_t)nh*L_ + i)*L_ + j0 + tx*4;
        *(__half2*)(dst)     = __floats2half2_rn(o0, o1);
        *(__half2*)(dst + 2) = __floats2half2_rn(o2, o3);
    }
}

// ================= kernel B: ray attention (R10 proven config) =================
// rr  = uw - 2 t.(R c) + |c|^2 ;  r.a' = t.(R a') - c.a'
// sum(p r) = R^T (sum p t) - s c  (fixed after loop)
#define ATTN_SMEM ((L_*KPAD + 4*L_)*4)   // vs + ts4 = 49152 B

__global__ void __launch_bounds__(256, 3) attn_kernel(
    const float* __restrict__ Rm, const float* __restrict__ t,
    const float* __restrict__ alpha, const float* __restrict__ beta)
{
    extern __shared__ float sm[];
    float*  vs  = sm;
    float4* ts4 = (float4*)(sm + L_*KPAD);

    const int tid = threadIdx.x;
    const int n = blockIdx.z, h = blockIdx.y;
    const int i0 = blockIdx.x * 64;

    const float* vb = g_vT + (size_t)(n*H_ + h)*V_*L_;
    for (int idx = tid; idx < QK_*L_; idx += 256) {
        int d = idx >> 9, j = idx & 511;
        vs[j*KPAD + d] = vb[idx];
    }
    for (int j = tid; j < L_; j += 256) {
        const float* tp = t + (size_t)(n*L_ + j)*3;
        ts4[j] = make_float4(tp[0], tp[1], tp[2], 0.f);
    }
    __syncthreads();

    const float LOG2E = 1.44269504089f;
    const float al = log1pf(expf(alpha[h])) * 0.70710678118f * LOG2E;
    const float be = log1pf(expf(beta[h]))  * 0.70710678118f * LOG2E;
    const int warp = tid >> 5, lane = tid & 31;

    #pragma unroll 1
    for (int pass = 0; pass < 8; pass++) {
        const int i = i0 + warp*8 + pass;

        float w1x, w1y, w1z, w2x, w2y, w2z, cw, ca, c0, c1, c2;
        {
            const float* Rp = Rm + (size_t)(n*L_ + i)*9;
            const float R00=Rp[0],R01=Rp[1],R02=Rp[2],
                        R10=Rp[3],R11=Rp[4],R12=Rp[5],
                        R20=Rp[6],R21=Rp[7],R22=Rp[8];
            const float4 ti = ts4[i];
            const float* bp_ = g_b + ((size_t)(n*H_ + h)*L_ + i)*3;
            c0 = R00*ti.x + R10*ti.y + R20*ti.z + bp_[0];
            c1 = R01*ti.x + R11*ti.y + R21*ti.z + bp_[1];
            c2 = R02*ti.x + R12*ti.y + R22*ti.z + bp_[2];
            cw = fmaf(c0,c0, fmaf(c1,c1, c2*c2));
            const float* ap = g_a + ((size_t)(n*H_ + h)*L_ + i)*3;
            float a0=ap[0], a1=ap[1], a2=ap[2];
            const float inv = 1.0f/(sqrtf(a0*a0+a1*a1+a2*a2) + EPS_);
            a0 *= inv; a1 *= inv; a2 *= inv;
            ca = fmaf(c0,a0, fmaf(c1,a1, c2*a2));
            w1x = -2.f*(R00*c0 + R01*c1 + R02*c2);
            w1y = -2.f*(R10*c0 + R11*c1 + R12*c2);
            w1z = -2.f*(R20*c0 + R21*c1 + R22*c2);
            w2x = R00*a0 + R01*a1 + R02*a2;
            w2y = R10*a0 + R11*a1 + R12*a2;
            w2z = R20*a0 + R21*a1 + R22*a2;
        }

        const float* uwp = g_uw + (size_t)(n*L_ + i)*L_;
        const __half* stp = g_st + ((size_t)(n*H_ + h)*L_ + i)*L_;

        float s=0.f, pt0=0.f, pt1=0.f, pt2=0.f, pth=0.f;
        float av[16];
        #pragma unroll
        for (int d = 0; d < 16; d++) av[d] = 0.f;

        #pragma unroll 2
        for (int it = 0; it < 16; it++) {
            const int j = it*32 + lane;
            const float uw = __ldg(uwp + j);
            const float st = __half2float(__ldg(stp + j));
            const float4 tj = ts4[j];

            float rr = fmaf(w1x,tj.x, fmaf(w1y,tj.y, fmaf(w1z,tj.z, uw + cw)));
            rr = fmaxf(rr, 1e-24f);
            const float ir = rsqrt_fast(rr);
            const float rs = rr * ir;
            const float rda = fmaf(w2x,tj.x, fmaf(w2y,tj.y, fmaf(w2z,tj.z, -ca)));
            const float th = acos_fast(rda * ir);
            float arg = fmaf(-al, rs, fmaf(-be, th, st));
            if (j == i) arg = -150.f;
            const float p = ex2_fast(arg);

            s += p;
            pt0 = fmaf(p, tj.x, pt0);
            pt1 = fmaf(p, tj.y, pt1);
            pt2 = fmaf(p, tj.z, pt2);
            pth = fmaf(p, th,  pth);

            const float4* vj = (const float4*)(vs + j*KPAD);
            const float4 v0 = vj[0], v1 = vj[1], v2 = vj[2], v3 = vj[3];
            av[0] =fmaf(p,v0.x,av[0]);  av[1] =fmaf(p,v0.y,av[1]);  av[2] =fmaf(p,v0.z,av[2]);  av[3] =fmaf(p,v0.w,av[3]);
            av[4] =fmaf(p,v1.x,av[4]);  av[5] =fmaf(p,v1.y,av[5]);  av[6] =fmaf(p,v1.z,av[6]);  av[7] =fmaf(p,v1.w,av[7]);
            av[8] =fmaf(p,v2.x,av[8]);  av[9] =fmaf(p,v2.y,av[9]);  av[10]=fmaf(p,v2.z,av[10]); av[11]=fmaf(p,v2.w,av[11]);
            av[12]=fmaf(p,v3.x,av[12]); av[13]=fmaf(p,v3.y,av[13]); av[14]=fmaf(p,v3.z,av[14]); av[15]=fmaf(p,v3.w,av[15]);
        }

        #pragma unroll
        for (int k = 0; k < 4; k++) {
            const int half = 8 >> k;
            const bool up = (lane >> k) & 1;
            #pragma unroll
            for (int t2 = 0; t2 < half; t2++) {
                float send = up ? av[t2] : av[t2 + half];
                float recv = __shfl_xor_sync(0xffffffffu, send, 1 << k);
                av[t2] = (up ? av[t2 + half] : av[t2]) + recv;
            }
        }
        av[0] += __shfl_xor_sync(0xffffffffu, av[0], 16);

        #pragma unroll
        for (int off = 16; off > 0; off >>= 1) {
            s   += __shfl_xor_sync(0xffffffffu, s,   off);
            pt0 += __shfl_xor_sync(0xffffffffu, pt0, off);
            pt1 += __shfl_xor_sync(0xffffffffu, pt1, off);
            pt2 += __shfl_xor_sync(0xffffffffu, pt2, off);
            pth += __shfl_xor_sync(0xffffffffu, pth, off);
        }
        const float inv = 1.0f / s;
        float* cc = g_cc + (size_t)(n*L_ + i)*CH_;
        if (lane < 16) {
            const int d = (int)(__brev((unsigned)lane) >> 28);
            cc[h*16 + d] = av[0] * inv;
        }
        if (lane == 0) {
            const float* Rp = Rm + (size_t)(n*L_ + i)*9;
            const float ra0 = (Rp[0]*pt0 + Rp[3]*pt1 + Rp[6]*pt2)*inv - c0;
            const float ra1 = (Rp[1]*pt0 + Rp[4]*pt1 + Rp[7]*pt2)*inv - c1;
            const float ra2 = (Rp[2]*pt0 + Rp[5]*pt1 + Rp[8]*pt2)*inv - c2;
            cc[384 + h*3 + 0] = ra0;
            cc[384 + h*3 + 1] = ra1;
            cc[384 + h*3 + 2] = ra2;
            cc[456 + h] = sqrtf(ra0*ra0 + ra1*ra1 + ra2*ra2);
            cc[480 + h] = pth*inv;
        }
    }
}

// ================= kernel C: output projection (16 rows/block) =================
__global__ void __launch_bounds__(256) out_kernel(
    const float* __restrict__ Wp, const float* __restrict__ bp,
    float* __restrict__ out)
{
    __shared__ __align__(16) float cs[16*CH_];
    const int tid = threadIdx.x;
    const int r0 = blockIdx.x * 16;

    for (int idx = tid; idx < 16*CH_; idx += 256)
        cs[idx] = g_cc[(size_t)r0*CH_ + idx];
    __syncthreads();

    const int col = tid & 127;
    const int rh  = tid >> 7;

    float acc[8];
    #pragma unroll
    for (int r = 0; r < 8; r++) acc[r] = 0.f;

    const float4* w4 = (const float4*)(Wp + (size_t)col*CH_);
    const float* csb = cs + rh*8*CH_;
    #pragma unroll 2
    for (int k4 = 0; k4 < CH_/4; k4++) {
        const float4 w = w4[k4];
        #pragma unroll
        for (int r = 0; r < 8; r++) {
            const float4 cv = ((const float4*)(csb + r*CH_))[k4];
            acc[r] += cv.x*w.x + cv.y*w.y + cv.z*w.z + cv.w*w.w;
        }
    }
    const float bbv = bp[col];
    #pragma unroll
    for (int r = 0; r < 8; r++)
        out[(size_t)(r0 + rh*8 + r)*HID_ + col] = acc[r] + bbv;
}

// ---------------- launch ----------------
extern "C" void kernel_launch(void* const* d_in, const int* in_sizes, int n_in,
                              void* d_out, int out_size)
{
    const float* x     = (const float*)d_in[0];
    const float* R     = (const float*)d_in[1];
    const float* t     = (const float*)d_in[2];
    const float* Wq    = (const float*)d_in[4];
    const float* Wk    = (const float*)d_in[5];
    const float* Wv    = (const float*)d_in[6];
    const float* bv    = (const float*)d_in[7];
    const float* Wa    = (const float*)d_in[8];
    const float* ba    = (const float*)d_in[9];
    const float* Wb    = (const float*)d_in[10];
    const float* bb    = (const float*)d_in[11];
    const float* Wp    = (const float*)d_in[12];
    const float* bp    = (const float*)d_in[13];
    const float* alpha = (const float*)d_in[14];
    const float* beta  = (const float*)d_in[15];

    u_kernel<<<dim3(64, N_), 256>>>(R, t);
    proj_kernel<<<dim3(16, 21), 256>>>(x, Wq, Wk, Wv, bv, Wa, ba, Wb, bb);
    st_kernel<<<dim3(8, 8, N_*H_), 256>>>();
    cudaFuncSetAttribute(attn_kernel, cudaFuncAttributeMaxDynamicSharedMemorySize, ATTN_SMEM);
    attn_kernel<<<dim3(8, H_, N_), 256, ATTN_SMEM>>>(R, t, alpha, beta);
    out_kernel<<<dim3(64), 256>>>(Wp, bp, (float*)d_out);
}